// round 16
// baseline (speedup 1.0000x reference)
#include <cuda_runtime.h>
#include <cstdint>

// Batched outer product: out[i, j*K + l] = x[i,j] * y[i,l]
// n=4096, m=256, k=256 → out row = 65536 f32 = 16384 float4.
// Pure store-bandwidth kernel (~1.07 GB written) at the HBM write wall.
// R15: identical to champion (block=1024, 1 row/CTA, smem x, float4 stores,
// grid=4096) except store policy .cs → .wt (write-through): no L2 dirty-line
// residency, steadier DRAM write stream.

static constexpr int M = 256;   // x row length
static constexpr int K = 256;   // y row length
static constexpr int ROW_F4 = (M * K) / 4;  // 16384 float4 per output row
static constexpr int BLK = 1024;

__global__ __launch_bounds__(BLK, 2)
void omul_kernel(const float* __restrict__ x,
                 const float* __restrict__ y,
                 float4* __restrict__ out)
{
    __shared__ float xs[M];

    const int row = blockIdx.x;
    const int t   = threadIdx.x;

    // Stage x row (first 256 threads); y float4 chunk fixed per thread:
    // (idx & 63) == (t & 63) for all iterations.
    if (t < M) xs[t] = x[(size_t)row * M + t];
    const float4 yv = reinterpret_cast<const float4*>(y + (size_t)row * K)[t & 63];
    __syncthreads();

    float4* o = out + (size_t)row * ROW_F4;

    // 16 iterations × 1024 threads = 16384 float4 stores, fully coalesced.
    #pragma unroll
    for (int i = 0; i < 16; i++) {
        const int idx = i * BLK + t;
        const float xv = xs[idx >> 6];        // smem broadcast, conflict-free
        float4 r;
        r.x = xv * yv.x;
        r.y = xv * yv.y;
        r.z = xv * yv.z;
        r.w = xv * yv.w;
        __stwt(&o[idx], r);                   // write-through streaming store
    }
}

extern "C" void kernel_launch(void* const* d_in, const int* in_sizes, int n_in,
                              void* d_out, int out_size)
{
    const float* x = (const float*)d_in[0];
    const float* y = (const float*)d_in[1];
    float4* out = (float4*)d_out;

    const int n = in_sizes[0] / M;  // 4096 rows
    omul_kernel<<<n, BLK>>>(x, y, out);
}

// round 17
// speedup vs baseline: 1.4446x; 1.4446x over previous
#include <cuda_runtime.h>
#include <cstdint>

// Batched outer product: out[i, j*K + l] = x[i,j] * y[i,l]
// n=4096, m=256, k=256 → out row = 65536 f32 = 16384 float4.
// Pure store-bandwidth kernel (~1.07 GB written) at the HBM write wall.
// FINAL (== R11 champion, 147.5us / 85.8% DRAM):
//   block=1024 (occ 2), 1 row/CTA, grid=4096, HW scheduling,
//   x staged in smem, y float4 in registers, float4 .cs streaming stores.
// Measured ledger: .cs >> default >> .wt; block 1024 > 512 > 256;
// 2 rows/CTA and persistent grids regress (L1tex queue saturation /
// tail imbalance). Residual gap to HBM spec is write-turnaround physics.

static constexpr int M = 256;   // x row length
static constexpr int K = 256;   // y row length
static constexpr int ROW_F4 = (M * K) / 4;  // 16384 float4 per output row
static constexpr int BLK = 1024;

__global__ __launch_bounds__(BLK, 2)
void omul_kernel(const float* __restrict__ x,
                 const float* __restrict__ y,
                 float4* __restrict__ out)
{
    __shared__ float xs[M];

    const int row = blockIdx.x;
    const int t   = threadIdx.x;

    // Stage x row (first 256 threads); y float4 chunk fixed per thread:
    // (idx & 63) == (t & 63) for all iterations.
    if (t < M) xs[t] = x[(size_t)row * M + t];
    const float4 yv = reinterpret_cast<const float4*>(y + (size_t)row * K)[t & 63];
    __syncthreads();

    float4* o = out + (size_t)row * ROW_F4;

    // 16 iterations × 1024 threads = 16384 float4 stores, fully coalesced.
    #pragma unroll
    for (int i = 0; i < 16; i++) {
        const int idx = i * BLK + t;
        const float xv = xs[idx >> 6];        // smem broadcast, conflict-free
        float4 r;
        r.x = xv * yv.x;
        r.y = xv * yv.y;
        r.z = xv * yv.z;
        r.w = xv * yv.w;
        __stcs(&o[idx], r);                   // evict-first streaming store
    }
}

extern "C" void kernel_launch(void* const* d_in, const int* in_sizes, int n_in,
                              void* d_out, int out_size)
{
    const float* x = (const float*)d_in[0];
    const float* y = (const float*)d_in[1];
    float4* out = (float4*)d_out;

    const int n = in_sizes[0] / M;  // 4096 rows
    omul_kernel<<<n, BLK>>>(x, y, out);
}